// round 15
// baseline (speedup 1.0000x reference)
#include <cuda_runtime.h>

#define NB      4
#define P       8192
#define NPTS    (NB * P)            // 32768
#define NBIN1   64
#define NBINS   (NBIN1 * NBIN1)     // 4096 per batch
#define GBINS   (NB * NBINS)        // 16384
#define XMIN    (-5.0f)
#define BINW    0.15625f            // 10 / 64
#define INVW    6.4f
#define NEG_INF (-3.402823466e38f)

#define TB_CAP  96                  // points per target bin (max expected ~63)
#define NHALF   (NB * NBIN1 * 2)    // 512 (batch,row,xhalf) source lists
#define SH_CAP  448                 // sources per half-row list (max expected ~310)
#define CAPW    1152                // SMEM window capacity (18.4 KB)

__device__ float4 d_tbin[GBINS * TB_CAP];   // target bins, fixed capacity (~25 MB)
__device__ int    d_tbc[GBINS];             // target bin counts (zero-init; re-zeroed by k_sum)
__device__ float4 d_shalf[NHALF * SH_CAP];  // source half-row lists
__device__ int    d_shc[NHALF];             // source list counts
__device__ float4 d_fb[NPTS];               // deferred sources (x,y,z,idx)
__device__ int    d_fbcnt;
__device__ float  g_nn[NPTS];               // nn_d2 by ORIGINAL source index

__device__ __forceinline__ int clampi(int v, int lo, int hi) {
    return v < lo ? lo : (v > hi ? hi : v);
}
__device__ __forceinline__ float warp_max(float v) {
    #pragma unroll
    for (int o = 16; o; o >>= 1)
        v = fmaxf(v, __shfl_xor_sync(0xffffffffu, v, o));
    return v;
}

// ---------------- K1: direct binning (no count/scan/scatter pipeline) ----------------
__global__ void k_bin(const float* __restrict__ src, const float* __restrict__ tgt) {
    int i = blockIdx.x * blockDim.x + threadIdx.x;   // 0..2*NPTS-1
    if (i < NPTS) {
        const float* t = tgt + (long)i * 3;
        float x = t[0], y = t[1], z = t[2];
        int b  = i / P;
        int bx = clampi((int)((x - XMIN) * INVW), 0, NBIN1 - 1);
        int by = clampi((int)((y - XMIN) * INVW), 0, NBIN1 - 1);
        int g  = b * NBINS + by * NBIN1 + bx;
        int pos = atomicAdd(&d_tbc[g], 1);
        if (pos < TB_CAP)
            d_tbin[g * TB_CAP + pos] =
                make_float4(x, y, z, -0.5f * (x * x + y * y + z * z));
    } else {
        int j = i - NPTS;
        const float* s = src + (long)j * 3;
        float x = s[0], y = s[1], z = s[2];
        int b  = j / P;
        int bx = clampi((int)((x - XMIN) * INVW), 0, NBIN1 - 1);
        int by = clampi((int)((y - XMIN) * INVW), 0, NBIN1 - 1);
        int h  = b * (NBIN1 * 2) + by * 2 + (bx >> 5);
        int pos = atomicAdd(&d_shc[h], 1);
        if (pos < SH_CAP)
            d_shalf[h * SH_CAP + pos] = make_float4(x, y, z, __int_as_float(j));
    }
}

// ---------------- K2: pass A — SMEM half-row window, thread-per-source ----------------
__global__ __launch_bounds__(128) void k_search() {
    __shared__ float4 pts[CAPW];
    __shared__ int2   bt[3 * 34];    // (smem_off, cnt) per window bin
    __shared__ int    s_total;

    const int tid   = threadIdx.x;
    const int b     = blockIdx.x;            // = batch*128 + row*2 + half
    const int batch = b >> 7;
    const int row   = (b & 127) >> 1;
    const int half  = b & 1;
    const int tbase = batch * NBINS;

    const int nsrc = min(d_shc[b], SH_CAP);
    if (nsrc == 0) return;

    const int r0 = clampi(row - 1, 0, NBIN1 - 1);
    const int r1 = clampi(row + 1, 0, NBIN1 - 1);
    const int c0 = clampi(half * 32 - 1, 0, NBIN1 - 1);
    const int c1 = clampi(half * 32 + 32, 0, NBIN1 - 1);
    const int nrows = r1 - r0 + 1;
    const int ncols = c1 - c0 + 1;
    const int nw    = nrows * ncols;         // <= 102

    if (tid == 0) s_total = 0;
    __syncthreads();

    // allocate packed SMEM offsets (order irrelevant: max is order-free)
    for (int wi = tid; wi < nw; wi += 128) {
        int r = r0 + wi / ncols, c = c0 + wi % ncols;
        int cnt = min(d_tbc[tbase + r * NBIN1 + c], TB_CAP);
        int off = atomicAdd(&s_total, cnt);
        bt[wi] = make_int2(off, cnt);
    }
    __syncthreads();

    if (s_total > CAPW) {                    // never expected; defer all (correct)
        for (int i = tid; i < nsrc; i += 128) {
            int pos = atomicAdd(&d_fbcnt, 1);
            d_fb[pos] = d_shalf[b * SH_CAP + i];
        }
        return;
    }

    // copy window bins into packed SMEM (warp per bin)
    const int wid = tid >> 5, lane = tid & 31;
    for (int wi = wid; wi < nw; wi += 4) {
        int r = r0 + wi / ncols, c = c0 + wi % ncols;
        int g = tbase + r * NBIN1 + c;
        int2 oc = bt[wi];
        for (int k = lane; k < oc.y; k += 32)
            pts[oc.x + k] = d_tbin[g * TB_CAP + k];
    }
    __syncthreads();

    // thread-per-source: scan its 3x3 from SMEM
    for (int i = tid; i < nsrc; i += 128) {
        float4 S = d_shalf[b * SH_CAP + i];
        const float sx = S.x, sy = S.y, sz = S.z;
        const float s2 = sx * sx + sy * sy + sz * sz;
        const int   bx = clampi((int)((sx - XMIN) * INVW), 0, NBIN1 - 1);
        const int   lc0 = clampi(bx - 1, c0, c1) - c0;
        const int   lc1 = clampi(bx + 1, c0, c1) - c0;

        float m = NEG_INF;
        for (int lr = 0; lr < nrows; lr++) {
            for (int lc = lc0; lc <= lc1; lc++) {
                int2 oc = bt[lr * ncols + lc];
                for (int k = 0; k < oc.y; k++) {
                    float4 t = pts[oc.x + k];
                    m = fmaxf(m, fmaf(sx, t.x, fmaf(sy, t.y, fmaf(sz, t.z, t.w))));
                }
            }
        }
        float d2 = fmaxf(0.0f, fmaf(-2.0f, m, s2));
        // any unscanned bin (Chebyshev >= 2) holds points >= 1*BINW away
        if (m != NEG_INF && d2 < BINW * BINW) {
            g_nn[__float_as_int(S.w)] = d2;   // proven exact
        } else {
            int pos = atomicAdd(&d_fbcnt, 1);
            d_fb[pos] = S;
        }
    }
}

// ---------------- K3: pass B — warp-per-source square scan over bins (exact) ----------------
#define WSCANSQ(R) do {                                                         \
    int _y0 = clampi(by - (R), 0, NBIN1 - 1);                                   \
    int _y1 = clampi(by + (R), 0, NBIN1 - 1);                                   \
    int _x0 = clampi(bx - (R), 0, NBIN1 - 1);                                   \
    int _x1 = clampi(bx + (R), 0, NBIN1 - 1);                                   \
    for (int _y = _y0; _y <= _y1; _y++)                                         \
        for (int _x = _x0; _x <= _x1; _x++) {                                   \
            int _g = tbase + _y * NBIN1 + _x;                                   \
            int _c = min(d_tbc[_g], TB_CAP);                                    \
            for (int _k = lane; _k < _c; _k += 32) {                            \
                float4 _t = d_tbin[_g * TB_CAP + _k];                           \
                m = fmaxf(m, fmaf(sx, _t.x, fmaf(sy, _t.y, fmaf(sz, _t.z, _t.w)))); \
            }                                                                   \
        }                                                                       \
} while (0)

__global__ __launch_bounds__(256) void k_fallback() {
    const int lane = threadIdx.x & 31;
    const int w    = blockIdx.x * 8 + (threadIdx.x >> 5);
    const int cnt  = d_fbcnt;

    for (int i = w; i < cnt; i += 512 * 8) {
        float4 S = d_fb[i];
        const float sx = S.x, sy = S.y, sz = S.z;
        const int   idx = __float_as_int(S.w);
        const float s2 = sx * sx + sy * sy + sz * sz;
        const int tbase = (idx >> 13) * NBINS;     // batch from original index
        const int bx = clampi((int)((sx - XMIN) * INVW), 0, NBIN1 - 1);
        const int by = clampi((int)((sy - XMIN) * INVW), 0, NBIN1 - 1);

        float m = NEG_INF;
        WSCANSQ(1);
        float mm = warp_max(m);
        int Rdone = 1;
        while (mm == NEG_INF && Rdone < NBIN1) {   // empty core: double until found
            Rdone *= 2;
            WSCANSQ(Rdone);
            mm = warp_max(m);
        }
        // any unscanned bin (Chebyshev >= R+1) holds points >= R*BINW away
        float d2 = fmaxf(0.0f, fmaf(-2.0f, mm, s2));
        int Rneed = (int)(sqrtf(d2) * INVW) + 1;
        if (Rneed > Rdone) {
            WSCANSQ(Rneed);                        // superset rescan; max idempotent
            mm = warp_max(m);
            d2 = fmaxf(0.0f, fmaf(-2.0f, mm, s2));
        }
        if (lane == 0) g_nn[idx] = d2;
    }
}
#undef WSCANSQ

// ---------------- K4: deterministic fixed-order sum + re-zero state ----------------
__global__ __launch_bounds__(1024) void k_sum(float* __restrict__ out) {
    __shared__ float red[1024];
    const int tid = threadIdx.x;
    float acc = 0.0f;
    #pragma unroll
    for (int c = 0; c < NPTS / 1024; c++)          // fixed ascending order
        acc += g_nn[c * 1024 + tid];
    red[tid] = acc;
    __syncthreads();
    #pragma unroll
    for (int st = 512; st > 0; st >>= 1) {
        if (tid < st) red[tid] += red[tid + st];
        __syncthreads();
    }
    if (tid == 0) { out[0] = red[0] * (1.0f / (float)NB); d_fbcnt = 0; }

    #pragma unroll
    for (int c = 0; c < GBINS / 1024; c++)
        d_tbc[c * 1024 + tid] = 0;
    if (tid < NHALF) d_shc[tid] = 0;
}

extern "C" void kernel_launch(void* const* d_in, const int* in_sizes, int n_in,
                              void* d_out, int out_size) {
    const float* src = (const float*)d_in[0];   // (4, 8192, 3) f32
    const float* tgt = (const float*)d_in[1];   // (4, 8192, 3) f32
    float* out = (float*)d_out;                  // scalar f32

    k_bin     <<<(2 * NPTS) / 256, 256>>>(src, tgt);
    k_search  <<<NHALF, 128>>>();
    k_fallback<<<512, 256>>>();
    k_sum     <<<1, 1024>>>(out);
}

// round 16
// speedup vs baseline: 8.7541x; 8.7541x over previous
#include <cuda_runtime.h>

#define NB          4
#define P1_PTS      8192
#define P2_PTS      8192
#define TPB         256
#define NSRC        8                        // sources per thread
#define SRC_PER_BLK (TPB * NSRC)             // 2048
#define TSPLIT      32
#define TILE        (P2_PTS / TSPLIT)        // 256 targets per block
#define NPAIR       (TILE / 2)               // 128
#define CHUNKS_PER_B (P1_PTS / SRC_PER_BLK)  // 4
#define NCHUNK      (NB * CHUNKS_PER_B)      // 16
#define NBLOCKS     (NCHUNK * TSPLIT)        // 512
#define NSRC_TOT    (NB * P1_PTS)            // 32768
#define NEG_INF     (-3.402823466e38f)

#define RED_TPB     256
#define RED_BLKS    (NSRC_TOT / RED_TPB)     // 128

__device__ float g_pmax[TSPLIT * NSRC_TOT];  // 4 MB
__device__ float g_sums[RED_BLKS];

__device__ __forceinline__ unsigned long long pack2(float a, float b) {
    unsigned long long r;
    asm("mov.b64 %0, {%1, %2};" : "=l"(r) : "f"(a), "f"(b));
    return r;
}
__device__ __forceinline__ unsigned long long ffma2(unsigned long long a,
                                                    unsigned long long b,
                                                    unsigned long long c) {
    unsigned long long d;
    asm("fma.rn.f32x2 %0, %1, %2, %3;" : "=l"(d) : "l"(a), "l"(b), "l"(c));
    return d;
}
__device__ __forceinline__ void unpack2(unsigned long long v, float& lo, float& hi) {
    asm("mov.b64 {%0, %1}, %2;" : "=f"(lo), "=f"(hi) : "l"(v));
}

__global__ __launch_bounds__(TPB, 3)
void chamfer_main(const float* __restrict__ src, const float* __restrict__ tgt) {
    // Pair-interleaved target tile: pair p -> [x0,x1, y0,y1, z0,z1, h0,h1]
    __shared__ float sh[TILE * 4];           // 4 KB

    const int tid   = threadIdx.x;
    const int chunk = blockIdx.x >> 5;       // 0..15
    const int split = blockIdx.x & 31;       // 0..31
    const int batch = chunk >> 2;            // 4 chunks per batch
    const int sbase = (chunk & 3) * SRC_PER_BLK;

    // ---- load & pack this block's 256-target slice (one element per thread) ----
    const float* tb = tgt + ((long)batch * P2_PTS + (long)split * TILE) * 3;
    {
        int j = tid;                          // TILE == TPB
        float x = tb[j * 3 + 0];
        float y = tb[j * 3 + 1];
        float z = tb[j * 3 + 2];
        float h = -0.5f * (x * x + y * y + z * z);
        float* b = sh + (j >> 1) * 8;
        int hl = j & 1;
        b[0 + hl] = x;
        b[2 + hl] = y;
        b[4 + hl] = z;
        b[6 + hl] = h;
    }

    // ---- eight source points per thread ----
    unsigned long long X[NSRC], Y[NSRC], Z[NSRC];
    const float* sp = src + ((long)batch * P1_PTS + sbase + tid) * 3;
    #pragma unroll
    for (int s = 0; s < NSRC; s++) {
        float x = sp[s * TPB * 3 + 0];
        float y = sp[s * TPB * 3 + 1];
        float z = sp[s * TPB * 3 + 2];
        X[s] = pack2(x, x);
        Y[s] = pack2(y, y);
        Z[s] = pack2(z, z);
    }

    float acc[NSRC];
    #pragma unroll
    for (int s = 0; s < NSRC; s++) acc[s] = NEG_INF;

    __syncthreads();

    const unsigned shb = (unsigned)__cvta_generic_to_shared(sh);

    // ---- inner loop: 1 target-pair x 8 sources, stage-ordered (validated R6 form) ----
    #pragma unroll 2
    for (int p = 0; p < NPAIR; p++) {
        unsigned a0 = shb + (unsigned)p * 32u;
        unsigned long long xP, yP, zP, hP;
        asm("ld.shared.v2.u64 {%0, %1}, [%2];" : "=l"(xP), "=l"(yP) : "r"(a0));
        asm("ld.shared.v2.u64 {%0, %1}, [%2];" : "=l"(zP), "=l"(hP) : "r"(a0 + 16u));

        unsigned long long t[NSRC];
        #pragma unroll
        for (int s = 0; s < NSRC; s++) t[s] = ffma2(Z[s], zP, hP);
        #pragma unroll
        for (int s = 0; s < NSRC; s++) t[s] = ffma2(Y[s], yP, t[s]);
        #pragma unroll
        for (int s = 0; s < NSRC; s++) t[s] = ffma2(X[s], xP, t[s]);
        #pragma unroll
        for (int s = 0; s < NSRC; s++) {
            float lo, hi;
            unpack2(t[s], lo, hi);
            acc[s] = fmaxf(acc[s], fmaxf(lo, hi));
        }
    }

    const int gsrc = batch * P1_PTS + sbase + tid;
    #pragma unroll
    for (int s = 0; s < NSRC; s++)
        g_pmax[split * NSRC_TOT + gsrc + s * TPB] = acc[s];
}

__global__ __launch_bounds__(RED_TPB)
void chamfer_reduce(const float* __restrict__ src) {
    __shared__ float red[RED_TPB];
    const int tid  = threadIdx.x;
    const int gsrc = blockIdx.x * RED_TPB + tid;

    float m = NEG_INF;
    #pragma unroll
    for (int s = 0; s < TSPLIT; s++)
        m = fmaxf(m, g_pmax[s * NSRC_TOT + gsrc]);

    const float* sp = src + (long)gsrc * 3;
    const float sx = sp[0], sy = sp[1], sz = sp[2];
    const float s2 = sx * sx + sy * sy + sz * sz;
    const float nn = fmaxf(0.0f, fmaf(-2.0f, m, s2));

    red[tid] = nn;
    __syncthreads();
    #pragma unroll
    for (int s = RED_TPB / 2; s > 0; s >>= 1) {
        if (tid < s) red[tid] += red[tid + s];
        __syncthreads();
    }
    if (tid == 0) g_sums[blockIdx.x] = red[0];
}

__global__ __launch_bounds__(RED_BLKS)
void chamfer_final(float* __restrict__ out) {
    __shared__ float red[RED_BLKS];
    const int tid = threadIdx.x;
    red[tid] = g_sums[tid];
    __syncthreads();
    #pragma unroll
    for (int s = RED_BLKS / 2; s > 0; s >>= 1) {
        if (tid < s) red[tid] += red[tid + s];
        __syncthreads();
    }
    if (tid == 0) out[0] = red[0] * (1.0f / (float)NB);
}

extern "C" void kernel_launch(void* const* d_in, const int* in_sizes, int n_in,
                              void* d_out, int out_size) {
    const float* src = (const float*)d_in[0];   // (4, 8192, 3) f32
    const float* tgt = (const float*)d_in[1];   // (4, 8192, 3) f32
    float* out = (float*)d_out;                  // scalar f32

    chamfer_main<<<NBLOCKS, TPB>>>(src, tgt);
    chamfer_reduce<<<RED_BLKS, RED_TPB>>>(src);
    chamfer_final<<<1, RED_BLKS>>>(out);
}